// round 16
// baseline (speedup 1.0000x reference)
#include <cuda_runtime.h>
#include <cuda_fp16.h>
#include <cstdint>

// BlockSparseAttention B=2,H=16,S=2048,D=128, block=128, NB=16
// Round 16: fully group-local pipeline (no CTA-wide sync in the j-loop).
//  - K/V fetched in q-column-group slices (warps (.,q) fetch exactly the
//    K-rows / V-cols they consume) -> visibility via bar.sync 5+q (128 thr).
//  - sums/P exchange stays on bar.sync 1+g (row groups).
//  - V(t+1) commit after the q-barrier (wait never blocks on fresh V).
//  - Q fp32->fp16 conversion moved into the main kernel prologue
//    (hidden under K/V cp.async wait); split prekernel handles only K,V.
//  - arithmetic identical to R14/15: Q,K,V,P single fp16; exp2 softmax.

#define B_  2
#define H_  16
#define S_  2048
#define D_  128
#define NB_ 16
#define NITEM 512
#define TOT (B_ * H_ * S_ * D_)

// smem byte offsets
#define Q_    0
#define K0_   32768
#define K1_   65536
#define V0_   98304
#define V1_   131072
#define P_    163840
#define SUMS_ 196608          // float [4][128]
#define SMEM_BYTES 198656

__device__ int g_rowbits[NB_];
__device__ int g_iorder[NB_];
__device__ int g_ctr;
__device__ __half gK[TOT], gV[TOT];

// ---- split (K,V) + prep kernel ----
__global__ __launch_bounds__(256)
void split_prep_kernel(const float* __restrict__ k,
                       const float* __restrict__ v,
                       const unsigned char* __restrict__ raw)
{
    if (blockIdx.x == 0) {
        __shared__ uint32_t sw64[64];
        __shared__ int mode;
        __shared__ int mv[256];
        int t = threadIdx.x;
        if (t < 64) sw64[t] = ((const uint32_t*)raw)[t];
        __syncthreads();
        if (t == 0) {
            int pat_i32 = 1, pat_f32 = 1;
            for (int w = 0; w < 64; w++) {
                uint32_t x = sw64[w];
                bool zero   = (x == 0u);
                bool i32one = (x == 1u);
                bool f32one = (x == 0x3F800000u);
                if (!(zero || i32one)) pat_i32 = 0;
                if (!(zero || f32one)) pat_f32 = 0;
            }
            mode = pat_i32 ? 1 : (pat_f32 ? 2 : 0);
        }
        __syncthreads();
        int val;
        if (mode == 1)      val = (((const int*)raw)[t] != 0);
        else if (mode == 2) val = (((const float*)raw)[t] != 0.0f);
        else                val = (raw[t] != 0);
        mv[t] = val;
        __syncthreads();
        if (t == 0) {
            int na[NB_], ord[NB_];
            for (int i = 0; i < NB_; i++) {
                int bits = 0;
                for (int j = 0; j < NB_; j++)
                    if (mv[i * NB_ + j]) bits |= 1 << j;
                g_rowbits[i] = bits;
                na[i] = __popc(bits);
                ord[i] = i;
            }
            for (int a = 1; a < NB_; a++) {   // LPT order
                int key = ord[a], kn = na[key], p = a - 1;
                while (p >= 0 && na[ord[p]] < kn) { ord[p + 1] = ord[p]; p--; }
                ord[p + 1] = key;
            }
            for (int x = 0; x < NB_; x++) g_iorder[x] = ord[x];
            g_ctr = 0;
        }
    }

    long idx = (long)blockIdx.x * 256 + threadIdx.x;
    if (idx >= TOT / 4) return;

    float4 x = ((const float4*)k)[idx];
    {
        __half2 a = __floats2half2_rn(x.x, x.y);
        __half2 b = __floats2half2_rn(x.z, x.w);
        ((uint2*)gK)[idx] = make_uint2(*(uint32_t*)&a, *(uint32_t*)&b);
    }
    x = ((const float4*)v)[idx];
    {
        __half2 a = __floats2half2_rn(x.x, x.y);
        __half2 b = __floats2half2_rn(x.z, x.w);
        ((uint2*)gV)[idx] = make_uint2(*(uint32_t*)&a, *(uint32_t*)&b);
    }
}

// ---------------- main kernel helpers ----------------
__device__ __forceinline__ uint32_t smem_u32(const void* p) {
    uint32_t a;
    asm("{ .reg .u64 t; cvta.to.shared.u64 t, %1; cvt.u32.u64 %0, t; }"
        : "=r"(a) : "l"(p));
    return a;
}
__device__ __forceinline__ uint32_t soff(int r, int c) {
    return (uint32_t)((r << 8) + ((((c >> 3) ^ (r & 7))) << 4) + ((c & 7) << 1));
}
__device__ __forceinline__ float fexp2(float x) {
    float y;
    asm("ex2.approx.f32 %0, %1;" : "=f"(y) : "f"(x));
    return y;
}
__device__ __forceinline__ void ldm4(uint32_t* r, uint32_t a) {
    asm volatile("ldmatrix.sync.aligned.m8n8.x4.shared.b16 {%0,%1,%2,%3}, [%4];"
        : "=r"(r[0]), "=r"(r[1]), "=r"(r[2]), "=r"(r[3]) : "r"(a));
}
__device__ __forceinline__ void ldm4t(uint32_t* r, uint32_t a) {
    asm volatile("ldmatrix.sync.aligned.m8n8.x4.trans.shared.b16 {%0,%1,%2,%3}, [%4];"
        : "=r"(r[0]), "=r"(r[1]), "=r"(r[2]), "=r"(r[3]) : "r"(a));
}
__device__ __forceinline__ void mma16(float* d, const uint32_t* a,
                                      uint32_t b0, uint32_t b1) {
    asm volatile("mma.sync.aligned.m16n8k16.row.col.f32.f16.f16.f32 "
        "{%0,%1,%2,%3},{%4,%5,%6,%7},{%8,%9},{%0,%1,%2,%3};"
        : "+f"(d[0]), "+f"(d[1]), "+f"(d[2]), "+f"(d[3])
        : "r"(a[0]), "r"(a[1]), "r"(a[2]), "r"(a[3]), "r"(b0), "r"(b1));
}
#define CPASYNC16(dst, src) \
    asm volatile("cp.async.cg.shared.global [%0], [%1], 16;" :: "r"(dst), "l"(src))
#define CPCOMMIT()  asm volatile("cp.async.commit_group;" ::: "memory")
#define CPWAIT0()   asm volatile("cp.async.wait_group 0;" ::: "memory")
#define GROUPBAR(id) \
    asm volatile("bar.sync %0, 128;" :: "r"(id) : "memory")

// q-group slice fetch: K rows [32q,32q+32), all cols. 512 granules / 128 thr.
__device__ __forceinline__ void fetch_k_slice(uint32_t dst_s,
                                              const __half* __restrict__ src,
                                              int qt, int q32) {
    #pragma unroll
    for (int it = 0; it < 4; it++) {
        int id  = qt + 128 * it;
        int row = q32 + (id >> 4);
        int c8  = id & 15;
        uint32_t dst = dst_s + (uint32_t)((row << 8) + (((c8 ^ (row & 7))) << 4));
        CPASYNC16(dst, src + (row << 7) + (c8 << 3));
    }
}
// q-group slice fetch: V cols [32q,32q+32) (granules 4q..4q+3), all 128 rows.
__device__ __forceinline__ void fetch_v_slice(uint32_t dst_s,
                                              const __half* __restrict__ src,
                                              int qt, int qq) {
    #pragma unroll
    for (int it = 0; it < 4; it++) {
        int id  = qt + 128 * it;
        int row = id >> 2;
        int c8  = 4 * qq + (id & 3);
        uint32_t dst = dst_s + (uint32_t)((row << 8) + (((c8 ^ (row & 7))) << 4));
        CPASYNC16(dst, src + (row << 7) + (c8 << 3));
    }
}

__global__ __launch_bounds__(512, 1)
void bsattn_kernel(const float* __restrict__ qf, float* __restrict__ out)
{
    extern __shared__ char smem[];
    const uint32_t sb = smem_u32(smem);
    float* sums = (float*)(smem + SUMS_);
    __shared__ int sh_w;

    const int tid  = threadIdx.x;
    const int warp = tid >> 5;
    const int lane = tid & 31;
    const int g    = warp >> 2;        // row group
    const int qq   = warp & 3;         // col group (= SMSP)
    const int g32  = g * 32;
    const int q32  = qq * 32;
    const int qr   = lane >> 2;
    const int qc   = lane & 3;
    const int qt   = g * 32 + lane;    // thread index within q-group (0..127)

    const int aRl = lane & 15;
    const int aCo = (lane & 16) >> 1;
    const int bRl = ((lane & 16) ? 8 : 0) + (lane & 7);
    const int bCo = (lane & 8) ? 8 : 0;
    const int vRl = ((lane & 8) ? 8 : 0) + (lane & 7);
    const int vCo = (lane & 16) ? 8 : 0;

    const float scale = 0.08838834764831845f * 1.4426950408889634f;

    float O[8][4];
    #pragma unroll
    for (int t = 0; t < 8; t++) { O[t][0]=0; O[t][1]=0; O[t][2]=0; O[t][3]=0; }
    float* prev_og = nullptr;

    for (;;) {
        if (tid == 0) sh_w = atomicAdd(&g_ctr, 1);
        __syncthreads();   // item boundary: all prior smem reads done; sh_w visible
        const int w = sh_w;
        const bool active = (w < NITEM);

        int i = 0, mrow = 0, j = -1;
        long base = 0;
        if (active) {
            i = g_iorder[w >> 5];
            const int bh = w & 31;
            base = (long)bh * S_ * D_;
            mrow = g_rowbits[i];
            j = __ffs(mrow) - 1;
            long koff = base + (long)j * 128 * D_;
            fetch_k_slice(sb + K0_, gK + koff, qt, q32);
            fetch_v_slice(sb + V0_, gV + koff, qt, qq);
            CPCOMMIT();
        }

        // ---- write previous item's O (overlaps prologue fetches) ----
        if (prev_og) {
            #pragma unroll
            for (int f = 0; f < 8; f++) {
                const int mb = f >> 2, d8 = f & 3;
                const int r0 = g32 + mb * 16 + qr;
                const int cc = q32 + d8 * 8 + qc * 2;
                *(float2*)(prev_og + r0 * D_ + cc)       = make_float2(O[f][0], O[f][1]);
                *(float2*)(prev_og + (r0 + 8) * D_ + cc) = make_float2(O[f][2], O[f][3]);
            }
        }
        if (!active) return;

        // ---- stage Q: fp32 LDG + scale + cvt + STS (hides K/V fetch) ----
        {
            const float* Qg = qf + base + (long)i * 128 * D_;
            #pragma unroll
            for (int it = 0; it < 8; it++) {
                int idx = tid + 512 * it;
                int r   = idx >> 5;
                int c4  = (idx & 31) << 2;
                float4 x = *(const float4*)(Qg + r * D_ + c4);
                __half2 a = __floats2half2_rn(x.x * scale, x.y * scale);
                __half2 b = __floats2half2_rn(x.z * scale, x.w * scale);
                *(uint2*)(smem + Q_ + soff(r, c4)) =
                    make_uint2(*(uint32_t*)&a, *(uint32_t*)&b);
            }
        }

        #pragma unroll
        for (int t = 0; t < 8; t++) { O[t][0]=0; O[t][1]=0; O[t][2]=0; O[t][3]=0; }

        CPWAIT0();
        __syncthreads();   // Q (generic STS) + K/V(j0) slices visible CTA-wide

        // ---- prologue QK(j0) -> S ----
        float S[8][4];
        #pragma unroll
        for (int x = 0; x < 8; x++) { S[x][0]=0; S[x][1]=0; S[x][2]=0; S[x][3]=0; }
        #pragma unroll
        for (int ks = 0; ks < 8; ks++) {
            const int kb = ks * 16;
            uint32_t ah[2][4], bF[2][4];
            ldm4(ah[0], sb + Q_ + soff(g32 + aRl,      kb + aCo));
            ldm4(ah[1], sb + Q_ + soff(g32 + 16 + aRl, kb + aCo));
            ldm4(bF[0], sb + K0_ + soff(q32 + bRl,      kb + bCo));
            ldm4(bF[1], sb + K0_ + soff(q32 + 16 + bRl, kb + bCo));
            #pragma unroll
            for (int mb = 0; mb < 2; mb++)
                #pragma unroll
                for (int nb = 0; nb < 2; nb++)
                    #pragma unroll
                    for (int h = 0; h < 2; h++)
                        mma16(S[mb * 4 + nb * 2 + h], ah[mb],
                              bF[nb][2*h], bF[nb][2*h+1]);
        }

        int c = 0;     // K(t) in kbuf[c], V(t) in vbuf[c]
        for (;;) {
            const int rem = mrow >> (j + 1);
            const int jn  = rem ? (j + __ffs(rem)) : -1;

            const uint32_t vbuf  = sb + V0_ + (uint32_t)c * 32768u;
            const uint32_t kbufn = sb + K0_ + (uint32_t)(c ^ 1) * 32768u;
            const uint32_t vbufn = sb + V0_ + (uint32_t)(c ^ 1) * 32768u;

            // ---- commit K(t+1) slice: target 2 fused-loops stale; q-group
            //      passed pre-fused QBAR(t-1) -> safe ----
            if (jn >= 0)
                fetch_k_slice(kbufn, gK + base + (long)jn * 128 * D_, qt, q32);
            CPCOMMIT();

            // ---- softmax: exp2 + quarter-local row sums ----
            float rsum[4];
            rsum[0] = rsum[1] = rsum[2] = rsum[3] = 0.0f;
            #pragma unroll
            for (int f = 0; f < 8; f++) {
                const int mb = f >> 2;
                S[f][0] = fexp2(S[f][0]);
                S[f][1] = fexp2(S[f][1]);
                S[f][2] = fexp2(S[f][2]);
                S[f][3] = fexp2(S[f][3]);
                rsum[mb * 2 + 0] += S[f][0] + S[f][1];
                rsum[mb * 2 + 1] += S[f][2] + S[f][3];
            }
            #pragma unroll
            for (int off = 1; off <= 2; off <<= 1) {
                rsum[0] += __shfl_xor_sync(0xffffffffu, rsum[0], off);
                rsum[1] += __shfl_xor_sync(0xffffffffu, rsum[1], off);
                rsum[2] += __shfl_xor_sync(0xffffffffu, rsum[2], off);
                rsum[3] += __shfl_xor_sync(0xffffffffu, rsum[3], off);
            }
            if (qc == 0) {
                #pragma unroll
                for (int t = 0; t < 4; t++) {
                    int r = g32 + (t >> 1) * 16 + (t & 1) * 8 + qr;
                    sums[qq * 128 + r] = rsum[t];
                }
            }
            GROUPBAR(1 + g);   // sums visible within row group

            // ---- normalize + pack P (own rows; P overwrite ordered by the
            //      sums barrier above: g-peers completed fused(t-1)) ----
            #pragma unroll
            for (int t = 0; t < 4; t++) {
                const int mb = t >> 1, hf = t & 1;
                const int r = g32 + mb * 16 + hf * 8 + qr;
                float inv = 1.0f / (sums[r] + sums[128 + r] +
                                    sums[256 + r] + sums[384 + r]);
                #pragma unroll
                for (int nb8 = 0; nb8 < 4; nb8++) {
                    const int f = mb * 4 + nb8;
                    const int e = hf * 2;
                    __half2 ph2 = __floats2half2_rn(S[f][e] * inv, S[f][e + 1] * inv);
                    uint32_t o = soff(r, q32 + nb8 * 8 + qc * 2);
                    *(uint32_t*)(smem + P_ + o) = *(uint32_t*)&ph2;
                }
            }
            GROUPBAR(1 + g);   // P visible within row group

            // ---- drain own async (V(t) slice + K(t+1) slice), then q-group
            //      rendezvous: slice data visible; peers past fused(t-1) ----
            CPWAIT0();
            GROUPBAR(5 + qq);

            // ---- commit V(t+1) slice (buffer read in fused(t-1) by this
            //      q-group only; ordered by the barrier above) ----
            if (jn >= 0)
                fetch_v_slice(vbufn, gV + base + (long)jn * 128 * D_, qt, qq);
            CPCOMMIT();

            if (jn >= 0) {
                // ---- fused: O += P(t) V(t)  AND  S = Q K(t+1)^T ----
                #pragma unroll
                for (int x = 0; x < 8; x++) { S[x][0]=0; S[x][1]=0; S[x][2]=0; S[x][3]=0; }
                #pragma unroll
                for (int ks = 0; ks < 8; ks++) {
                    const int kb = ks * 16;
                    uint32_t ph[2][4], vF[2][4], ah[2][4], bF[2][4];
                    ldm4(ph[0], sb + P_ + soff(g32 + aRl,      kb + aCo));
                    ldm4(ph[1], sb + P_ + soff(g32 + 16 + aRl, kb + aCo));
                    ldm4t(vF[0], vbuf + soff(kb + vRl, q32 + vCo));
                    ldm4t(vF[1], vbuf + soff(kb + vRl, q32 + 16 + vCo));
                    ldm4(ah[0], sb + Q_ + soff(g32 + aRl,      kb + aCo));
                    ldm4(ah[1], sb + Q_ + soff(g32 + 16 + aRl, kb + aCo));
                    ldm4(bF[0], kbufn + soff(q32 + bRl,      kb + bCo));
                    ldm4(bF[1], kbufn + soff(q32 + 16 + bRl, kb + bCo));
                    #pragma unroll
                    for (int mb = 0; mb < 2; mb++)
                        #pragma unroll
                        for (int nb = 0; nb < 2; nb++)
                            #pragma unroll
                            for (int h = 0; h < 2; h++) {
                                mma16(O[mb * 4 + nb * 2 + h], ph[mb],
                                      vF[nb][2*h], vF[nb][2*h+1]);
                                mma16(S[mb * 4 + nb * 2 + h], ah[mb],
                                      bF[nb][2*h], bF[nb][2*h+1]);
                            }
                }
                c ^= 1;
                j = jn;
            } else {
                // ---- final: PV only ----
                #pragma unroll
                for (int ks = 0; ks < 8; ks++) {
                    const int kb = ks * 16;
                    uint32_t ph[2][4], vF[2][4];
                    ldm4(ph[0], sb + P_ + soff(g32 + aRl,      kb + aCo));
                    ldm4(ph[1], sb + P_ + soff(g32 + 16 + aRl, kb + aCo));
                    ldm4t(vF[0], vbuf + soff(kb + vRl, q32 + vCo));
                    ldm4t(vF[1], vbuf + soff(kb + vRl, q32 + 16 + vCo));
                    #pragma unroll
                    for (int mb = 0; mb < 2; mb++)
                        #pragma unroll
                        for (int db = 0; db < 2; db++)
                            #pragma unroll
                            for (int h = 0; h < 2; h++)
                                mma16(O[mb * 4 + db * 2 + h], ph[mb],
                                      vF[db][2*h], vF[db][2*h+1]);
                }
                break;
            }
        }

        prev_og = out + base + (long)i * 128 * D_;
    }
}

extern "C" void kernel_launch(void* const* d_in, const int* in_sizes, int n_in,
                              void* d_out, int out_size)
{
    const float* q = (const float*)d_in[0];
    const float* k = (const float*)d_in[1];
    const float* v = (const float*)d_in[2];
    const unsigned char* mask_raw = (const unsigned char*)d_in[3];
    float* out = (float*)d_out;

    split_prep_kernel<<<(TOT / 4 + 255) / 256, 256>>>(k, v, mask_raw);

    cudaFuncSetAttribute(bsattn_kernel,
                         cudaFuncAttributeMaxDynamicSharedMemorySize, SMEM_BYTES);

    bsattn_kernel<<<148, 512, SMEM_BYTES>>>(q, out);
}

// round 17
// speedup vs baseline: 1.0671x; 1.0671x over previous
#include <cuda_runtime.h>
#include <cuda_fp16.h>
#include <cstdint>

// BlockSparseAttention B=2,H=16,S=2048,D=128, block=128, NB=16
// Round 17: R14 main loop (proven fastest) + K/V-only split prekernel +
// Q fp32->fp16 conversion in the item prologue (hidden under K/V cp.async).
//  - fused PV(t)+QK(t+1) MMA region, 2 CTA syncs per j (R14 structure)
//  - full-tile coalesced cp.async fetches (no slicing)
//  - arithmetic identical to R12-R16: Q,K,V,P single fp16; exp2 softmax.

#define B_  2
#define H_  16
#define S_  2048
#define D_  128
#define NB_ 16
#define NITEM 512
#define TOT (B_ * H_ * S_ * D_)

// smem byte offsets
#define Q_    0
#define K0_   32768
#define K1_   65536
#define V0_   98304
#define V1_   131072
#define P_    163840
#define SUMS_ 196608          // float [4][128]
#define SMEM_BYTES 198656

__device__ int g_rowbits[NB_];
__device__ int g_iorder[NB_];
__device__ int g_ctr;
__device__ __half gK[TOT], gV[TOT];

// ---- split (K,V) + prep kernel ----
__global__ __launch_bounds__(256)
void split_prep_kernel(const float* __restrict__ k,
                       const float* __restrict__ v,
                       const unsigned char* __restrict__ raw)
{
    if (blockIdx.x == 0) {
        __shared__ uint32_t sw64[64];
        __shared__ int mode;
        __shared__ int mv[256];
        int t = threadIdx.x;
        if (t < 64) sw64[t] = ((const uint32_t*)raw)[t];
        __syncthreads();
        if (t == 0) {
            int pat_i32 = 1, pat_f32 = 1;
            for (int w = 0; w < 64; w++) {
                uint32_t x = sw64[w];
                bool zero   = (x == 0u);
                bool i32one = (x == 1u);
                bool f32one = (x == 0x3F800000u);
                if (!(zero || i32one)) pat_i32 = 0;
                if (!(zero || f32one)) pat_f32 = 0;
            }
            mode = pat_i32 ? 1 : (pat_f32 ? 2 : 0);
        }
        __syncthreads();
        int val;
        if (mode == 1)      val = (((const int*)raw)[t] != 0);
        else if (mode == 2) val = (((const float*)raw)[t] != 0.0f);
        else                val = (raw[t] != 0);
        mv[t] = val;
        __syncthreads();
        if (t == 0) {
            int na[NB_], ord[NB_];
            for (int i = 0; i < NB_; i++) {
                int bits = 0;
                for (int j = 0; j < NB_; j++)
                    if (mv[i * NB_ + j]) bits |= 1 << j;
                g_rowbits[i] = bits;
                na[i] = __popc(bits);
                ord[i] = i;
            }
            for (int a = 1; a < NB_; a++) {   // LPT order
                int key = ord[a], kn = na[key], p = a - 1;
                while (p >= 0 && na[ord[p]] < kn) { ord[p + 1] = ord[p]; p--; }
                ord[p + 1] = key;
            }
            for (int x = 0; x < NB_; x++) g_iorder[x] = ord[x];
            g_ctr = 0;
        }
    }

    long idx = (long)blockIdx.x * 256 + threadIdx.x;
    if (idx >= TOT / 4) return;

    float4 x = ((const float4*)k)[idx];
    {
        __half2 a = __floats2half2_rn(x.x, x.y);
        __half2 b = __floats2half2_rn(x.z, x.w);
        ((uint2*)gK)[idx] = make_uint2(*(uint32_t*)&a, *(uint32_t*)&b);
    }
    x = ((const float4*)v)[idx];
    {
        __half2 a = __floats2half2_rn(x.x, x.y);
        __half2 b = __floats2half2_rn(x.z, x.w);
        ((uint2*)gV)[idx] = make_uint2(*(uint32_t*)&a, *(uint32_t*)&b);
    }
}

// ---------------- main kernel helpers ----------------
__device__ __forceinline__ uint32_t smem_u32(const void* p) {
    uint32_t a;
    asm("{ .reg .u64 t; cvta.to.shared.u64 t, %1; cvt.u32.u64 %0, t; }"
        : "=r"(a) : "l"(p));
    return a;
}
__device__ __forceinline__ uint32_t soff(int r, int c) {
    return (uint32_t)((r << 8) + ((((c >> 3) ^ (r & 7))) << 4) + ((c & 7) << 1));
}
__device__ __forceinline__ float fexp2(float x) {
    float y;
    asm("ex2.approx.f32 %0, %1;" : "=f"(y) : "f"(x));
    return y;
}
__device__ __forceinline__ void ldm4(uint32_t* r, uint32_t a) {
    asm volatile("ldmatrix.sync.aligned.m8n8.x4.shared.b16 {%0,%1,%2,%3}, [%4];"
        : "=r"(r[0]), "=r"(r[1]), "=r"(r[2]), "=r"(r[3]) : "r"(a));
}
__device__ __forceinline__ void ldm4t(uint32_t* r, uint32_t a) {
    asm volatile("ldmatrix.sync.aligned.m8n8.x4.trans.shared.b16 {%0,%1,%2,%3}, [%4];"
        : "=r"(r[0]), "=r"(r[1]), "=r"(r[2]), "=r"(r[3]) : "r"(a));
}
__device__ __forceinline__ void mma16(float* d, const uint32_t* a,
                                      uint32_t b0, uint32_t b1) {
    asm volatile("mma.sync.aligned.m16n8k16.row.col.f32.f16.f16.f32 "
        "{%0,%1,%2,%3},{%4,%5,%6,%7},{%8,%9},{%0,%1,%2,%3};"
        : "+f"(d[0]), "+f"(d[1]), "+f"(d[2]), "+f"(d[3])
        : "r"(a[0]), "r"(a[1]), "r"(a[2]), "r"(a[3]), "r"(b0), "r"(b1));
}
#define CPASYNC16(dst, src) \
    asm volatile("cp.async.cg.shared.global [%0], [%1], 16;" :: "r"(dst), "l"(src))
#define CPCOMMIT()  asm volatile("cp.async.commit_group;" ::: "memory")
#define CPWAIT1()   asm volatile("cp.async.wait_group 1;" ::: "memory")

__device__ __forceinline__ void fetch_tile(uint32_t dst_s,
                                           const __half* __restrict__ src,
                                           int tid) {
    #pragma unroll
    for (int it = 0; it < 4; it++) {
        int g  = tid + 512 * it;
        int r  = g >> 4;
        int c8 = g & 15;
        uint32_t dst = dst_s + (uint32_t)((r << 8) + (((c8 ^ (r & 7))) << 4));
        CPASYNC16(dst, src + (r << 7) + (c8 << 3));
    }
}

__global__ __launch_bounds__(512, 1)
void bsattn_kernel(const float* __restrict__ qf, float* __restrict__ out)
{
    extern __shared__ char smem[];
    const uint32_t sb = smem_u32(smem);
    float* sums = (float*)(smem + SUMS_);
    __shared__ int sh_w;

    const int tid  = threadIdx.x;
    const int warp = tid >> 5;
    const int lane = tid & 31;
    const int g    = warp >> 2;
    const int qq   = warp & 3;
    const int g32  = g * 32;
    const int q32  = qq * 32;
    const int qr   = lane >> 2;
    const int qc   = lane & 3;

    const int aRl = lane & 15;
    const int aCo = (lane & 16) >> 1;
    const int bRl = ((lane & 16) ? 8 : 0) + (lane & 7);
    const int bCo = (lane & 8) ? 8 : 0;
    const int vRl = ((lane & 8) ? 8 : 0) + (lane & 7);
    const int vCo = (lane & 16) ? 8 : 0;

    const float scale = 0.08838834764831845f * 1.4426950408889634f;

    for (;;) {
        if (tid == 0) sh_w = atomicAdd(&g_ctr, 1);
        __syncthreads();       // item boundary: prior smem reads done; sh_w visible
        const int w = sh_w;
        if (w >= NITEM) return;

        const int i  = g_iorder[w >> 5];
        const int bh = w & 31;
        const long base = (long)bh * S_ * D_;
        const int mrow = g_rowbits[i];

        int j = __ffs(mrow) - 1;

        // ---- prologue: commit [K(j0)] and [V(j0)] cp.async groups ----
        {
            long koff = base + (long)j * 128 * D_;
            fetch_tile(sb + K0_, gK + koff, tid);
            CPCOMMIT();
            fetch_tile(sb + V0_, gV + koff, tid);
            CPCOMMIT();
        }

        // ---- stage Q: fp32 LDG + scale + cvt + STS (hides K/V flight) ----
        {
            const float* Qg = qf + base + (long)i * 128 * D_;
            #pragma unroll
            for (int it = 0; it < 8; it++) {
                int idx = tid + 512 * it;
                int r   = idx >> 5;
                int c4  = (idx & 31) << 2;
                float4 x = *(const float4*)(Qg + r * D_ + c4);
                __half2 a = __floats2half2_rn(x.x * scale, x.y * scale);
                __half2 b = __floats2half2_rn(x.z * scale, x.w * scale);
                *(uint2*)(smem + Q_ + soff(r, c4)) =
                    make_uint2(*(uint32_t*)&a, *(uint32_t*)&b);
            }
        }

        float O[8][4];
        #pragma unroll
        for (int t = 0; t < 8; t++) { O[t][0]=0; O[t][1]=0; O[t][2]=0; O[t][3]=0; }

        CPWAIT1();             // K(j0) resident (V0 still in flight)
        __syncthreads();       // + Q STS visible CTA-wide

        // ---- prologue QK(j0) -> S ----
        float S[8][4];
        #pragma unroll
        for (int x = 0; x < 8; x++) { S[x][0]=0; S[x][1]=0; S[x][2]=0; S[x][3]=0; }
        #pragma unroll
        for (int ks = 0; ks < 8; ks++) {
            const int kb = ks * 16;
            uint32_t ah[2][4], bF[2][4];
            ldm4(ah[0], sb + Q_ + soff(g32 + aRl,      kb + aCo));
            ldm4(ah[1], sb + Q_ + soff(g32 + 16 + aRl, kb + aCo));
            ldm4(bF[0], sb + K0_ + soff(q32 + bRl,      kb + bCo));
            ldm4(bF[1], sb + K0_ + soff(q32 + 16 + bRl, kb + bCo));
            #pragma unroll
            for (int mb = 0; mb < 2; mb++)
                #pragma unroll
                for (int nb = 0; nb < 2; nb++)
                    #pragma unroll
                    for (int h = 0; h < 2; h++)
                        mma16(S[mb * 4 + nb * 2 + h], ah[mb],
                              bF[nb][2*h], bF[nb][2*h+1]);
        }

        int c = 0;     // K(t) in kbuf[c], V(t) in vbuf[c]
        for (;;) {
            const int rem = mrow >> (j + 1);
            const int jn  = rem ? (j + __ffs(rem)) : -1;

            const uint32_t vbuf  = sb + V0_ + (uint32_t)c * 32768u;
            const uint32_t kbufn = sb + K0_ + (uint32_t)(c ^ 1) * 32768u;
            const uint32_t vbufn = sb + V0_ + (uint32_t)(c ^ 1) * 32768u;

            // ---- commit K(t+1): target 2 fused-loops stale (safe) ----
            if (jn >= 0) {
                long koff = base + (long)jn * 128 * D_;
                fetch_tile(kbufn, gK + koff, tid);
            }
            CPCOMMIT();

            // ---- softmax: exp2 + quarter-local row sums ----
            float rsum[4];
            rsum[0] = rsum[1] = rsum[2] = rsum[3] = 0.0f;
            #pragma unroll
            for (int f = 0; f < 8; f++) {
                const int mb = f >> 2;
                S[f][0] = fexp2(S[f][0]);
                S[f][1] = fexp2(S[f][1]);
                S[f][2] = fexp2(S[f][2]);
                S[f][3] = fexp2(S[f][3]);
                rsum[mb * 2 + 0] += S[f][0] + S[f][1];
                rsum[mb * 2 + 1] += S[f][2] + S[f][3];
            }
            #pragma unroll
            for (int off = 1; off <= 2; off <<= 1) {
                rsum[0] += __shfl_xor_sync(0xffffffffu, rsum[0], off);
                rsum[1] += __shfl_xor_sync(0xffffffffu, rsum[1], off);
                rsum[2] += __shfl_xor_sync(0xffffffffu, rsum[2], off);
                rsum[3] += __shfl_xor_sync(0xffffffffu, rsum[3], off);
            }
            if (qc == 0) {
                #pragma unroll
                for (int t = 0; t < 4; t++) {
                    int r = g32 + (t >> 1) * 16 + (t & 1) * 8 + qr;
                    sums[qq * 128 + r] = rsum[t];
                }
            }
            __syncthreads();   // sync#1: sums visible; fused(t-1) done CTA-wide

            // ---- commit V(t+1) (vbuf[c^1] drained per sync#1) ----
            if (jn >= 0) {
                long voff = base + (long)jn * 128 * D_;
                fetch_tile(vbufn, gV + voff, tid);
            }
            CPCOMMIT();

            // ---- normalize + pack P (single fp16) ----
            #pragma unroll
            for (int t = 0; t < 4; t++) {
                const int mb = t >> 1, hf = t & 1;
                const int r = g32 + mb * 16 + hf * 8 + qr;
                float inv = 1.0f / (sums[r] + sums[128 + r] +
                                    sums[256 + r] + sums[384 + r]);
                #pragma unroll
                for (int nb8 = 0; nb8 < 4; nb8++) {
                    const int f = mb * 4 + nb8;
                    const int e = hf * 2;
                    __half2 ph2 = __floats2half2_rn(S[f][e] * inv, S[f][e + 1] * inv);
                    uint32_t o = soff(r, q32 + nb8 * 8 + qc * 2);
                    *(uint32_t*)(smem + P_ + o) = *(uint32_t*)&ph2;
                }
            }

            // ---- wait: pending [V(t), K(t+1), V(t+1)] -> all but last done ----
            CPWAIT1();
            __syncthreads();   // sync#2: V(t), K(t+1), P visible

            if (jn >= 0) {
                // ---- fused: O += P(t) V(t)  AND  S = Q K(t+1)^T ----
                #pragma unroll
                for (int x = 0; x < 8; x++) { S[x][0]=0; S[x][1]=0; S[x][2]=0; S[x][3]=0; }
                #pragma unroll
                for (int ks = 0; ks < 8; ks++) {
                    const int kb = ks * 16;
                    uint32_t ph[2][4], vF[2][4], ah[2][4], bF[2][4];
                    ldm4(ph[0], sb + P_ + soff(g32 + aRl,      kb + aCo));
                    ldm4(ph[1], sb + P_ + soff(g32 + 16 + aRl, kb + aCo));
                    ldm4t(vF[0], vbuf + soff(kb + vRl, q32 + vCo));
                    ldm4t(vF[1], vbuf + soff(kb + vRl, q32 + 16 + vCo));
                    ldm4(ah[0], sb + Q_ + soff(g32 + aRl,      kb + aCo));
                    ldm4(ah[1], sb + Q_ + soff(g32 + 16 + aRl, kb + aCo));
                    ldm4(bF[0], kbufn + soff(q32 + bRl,      kb + bCo));
                    ldm4(bF[1], kbufn + soff(q32 + 16 + bRl, kb + bCo));
                    #pragma unroll
                    for (int mb = 0; mb < 2; mb++)
                        #pragma unroll
                        for (int nb = 0; nb < 2; nb++)
                            #pragma unroll
                            for (int h = 0; h < 2; h++) {
                                mma16(O[mb * 4 + nb * 2 + h], ph[mb],
                                      vF[nb][2*h], vF[nb][2*h+1]);
                                mma16(S[mb * 4 + nb * 2 + h], ah[mb],
                                      bF[nb][2*h], bF[nb][2*h+1]);
                            }
                }
                c ^= 1;
                j = jn;
            } else {
                // ---- final: PV only ----
                #pragma unroll
                for (int ks = 0; ks < 8; ks++) {
                    const int kb = ks * 16;
                    uint32_t ph[2][4], vF[2][4];
                    ldm4(ph[0], sb + P_ + soff(g32 + aRl,      kb + aCo));
                    ldm4(ph[1], sb + P_ + soff(g32 + 16 + aRl, kb + aCo));
                    ldm4t(vF[0], vbuf + soff(kb + vRl, q32 + vCo));
                    ldm4t(vF[1], vbuf + soff(kb + vRl, q32 + 16 + vCo));
                    #pragma unroll
                    for (int mb = 0; mb < 2; mb++)
                        #pragma unroll
                        for (int db = 0; db < 2; db++)
                            #pragma unroll
                            for (int h = 0; h < 2; h++)
                                mma16(O[mb * 4 + db * 2 + h], ph[mb],
                                      vF[db][2*h], vF[db][2*h+1]);
                }
                break;
            }
        }

        // ---- write O tile (disjoint per warp) ----
        float* Og = out + base + (long)i * 128 * D_;
        #pragma unroll
        for (int f = 0; f < 8; f++) {
            const int mb = f >> 2, d8 = f & 3;
            const int r0 = g32 + mb * 16 + qr;
            const int cc = q32 + d8 * 8 + qc * 2;
            *(float2*)(Og + r0 * D_ + cc)       = make_float2(O[f][0], O[f][1]);
            *(float2*)(Og + (r0 + 8) * D_ + cc) = make_float2(O[f][2], O[f][3]);
        }
    }
}

extern "C" void kernel_launch(void* const* d_in, const int* in_sizes, int n_in,
                              void* d_out, int out_size)
{
    const float* q = (const float*)d_in[0];
    const float* k = (const float*)d_in[1];
    const float* v = (const float*)d_in[2];
    const unsigned char* mask_raw = (const unsigned char*)d_in[3];
    float* out = (float*)d_out;

    split_prep_kernel<<<(TOT / 4 + 255) / 256, 256>>>(k, v, mask_raw);

    cudaFuncSetAttribute(bsattn_kernel,
                         cudaFuncAttributeMaxDynamicSharedMemorySize, SMEM_BYTES);

    bsattn_kernel<<<148, 512, SMEM_BYTES>>>(q, out);
}